// round 1
// baseline (speedup 1.0000x reference)
#include <cuda_runtime.h>
#include <cuda_bf16.h>

#define N_NODES 49998
#define E_EDGES 800000
#define HH0 8
#define DIN 128
#define DOUT 32
#define F0DIM (HH0*DOUT)   /* 256 */

// -------- scratch (device globals; no allocation allowed) --------
__device__ float g_f0 [N_NODES*F0DIM];
__device__ float g_out0[N_NODES*F0DIM];   // after finalize0: h0 = elu(out0+b0)
__device__ float g_el0[N_NODES*HH0];
__device__ float g_er0[N_NODES*HH0];
__device__ float g_m0 [N_NODES*HH0];
__device__ float g_d0 [N_NODES*HH0];
__device__ float g_f1 [N_NODES*DOUT];
__device__ float g_out1[N_NODES*DOUT];
__device__ float g_h1 [N_NODES*DOUT];
__device__ float g_el1[N_NODES];
__device__ float g_er1[N_NODES];
__device__ float g_m1 [N_NODES];
__device__ float g_d1 [N_NODES];

// -------- helpers --------
__device__ __forceinline__ void atomicMaxF(float* addr, float v) {
    if (v >= 0.f) atomicMax((int*)addr, __float_as_int(v));
    else          atomicMin((unsigned int*)addr, __float_as_uint(v));
}

__device__ __forceinline__ void redAdd4(float* addr, float a, float b, float c, float d) {
    asm volatile("red.global.add.v4.f32 [%0], {%1,%2,%3,%4};"
                 :: "l"(addr), "f"(a), "f"(b), "f"(c), "f"(d) : "memory");
}

__device__ __forceinline__ float lrelu02(float v) { return v > 0.f ? v : 0.2f * v; }

// -------- init --------
__global__ void init0_k(int n) {
    int i = blockIdx.x * blockDim.x + threadIdx.x;
    if (i < n * F0DIM) g_out0[i] = 0.f;
    if (i < n * HH0) { g_m0[i] = __int_as_float(0xff800000); g_d0[i] = 0.f; }
}
__global__ void init1_k(int n) {
    int i = blockIdx.x * blockDim.x + threadIdx.x;
    if (i < n * DOUT) g_out1[i] = 0.f;
    if (i < n) { g_m1[i] = __int_as_float(0xff800000); g_d1[i] = 0.f; }
}

// -------- layer-0 GEMM: f0 = x @ W0, plus el0/er0 head scores --------
// block = 256 threads (one per output column), 32 nodes per block.
__global__ void gemm0_k(const float* __restrict__ x, const float* __restrict__ W0,
                        const float* __restrict__ al0, const float* __restrict__ ar0, int n) {
    __shared__ float xs[DIN][36];   // xs[k][node], pad 36 -> 16B-aligned rows, low conflict
    int n0 = blockIdx.x * 32;
    int t  = threadIdx.x;
    for (int i = t; i < 32 * DIN; i += 256) {
        int r = i >> 7, c = i & 127;
        int node = n0 + r;
        xs[c][r] = (node < n) ? x[node * DIN + c] : 0.f;
    }
    __syncthreads();

    float acc[32];
    #pragma unroll
    for (int i = 0; i < 32; i++) acc[i] = 0.f;

    for (int k = 0; k < DIN; k++) {
        float w = W0[k * F0DIM + t];
        const float4* xp = (const float4*)&xs[k][0];
        #pragma unroll
        for (int ii = 0; ii < 8; ii++) {
            float4 xv = xp[ii];
            acc[4*ii+0] = fmaf(xv.x, w, acc[4*ii+0]);
            acc[4*ii+1] = fmaf(xv.y, w, acc[4*ii+1]);
            acc[4*ii+2] = fmaf(xv.z, w, acc[4*ii+2]);
            acc[4*ii+3] = fmaf(xv.w, w, acc[4*ii+3]);
        }
    }

    int h = t >> 5, lane = t & 31;
    float alv = al0[t], arv = ar0[t];
    #pragma unroll
    for (int i = 0; i < 32; i++) {
        int node = n0 + i;
        float fv = acc[i];
        float pl = fv * alv, pr = fv * arv;
        #pragma unroll
        for (int off = 16; off; off >>= 1) {
            pl += __shfl_xor_sync(0xffffffffu, pl, off);
            pr += __shfl_xor_sync(0xffffffffu, pr, off);
        }
        if (node < n) {
            g_f0[node * F0DIM + t] = fv;
            if (lane == 0) { g_el0[node * HH0 + h] = pl; g_er0[node * HH0 + h] = pr; }
        }
    }
}

// -------- layer-1 GEMM: f1 = h0 @ W1, plus el1/er1 --------
// block = 256 threads: 8 nodes x 32 columns; warp == node.
__global__ void gemm1_k(const float* __restrict__ W1,
                        const float* __restrict__ al1, const float* __restrict__ ar1, int n) {
    __shared__ float hs[8][F0DIM];
    int n0 = blockIdx.x * 8;
    int t  = threadIdx.x;
    for (int i = t; i < 8 * F0DIM; i += 256) {
        int r = i >> 8, c = i & 255;
        int node = n0 + r;
        hs[r][c] = (node < n) ? g_out0[node * F0DIM + c] : 0.f;
    }
    __syncthreads();

    int j = t & 31, sub = t >> 5;
    float acc = 0.f;
    #pragma unroll 8
    for (int k = 0; k < F0DIM; k++) acc = fmaf(hs[sub][k], W1[k * DOUT + j], acc);

    float pl = acc * al1[j], pr = acc * ar1[j];
    #pragma unroll
    for (int off = 16; off; off >>= 1) {
        pl += __shfl_xor_sync(0xffffffffu, pl, off);
        pr += __shfl_xor_sync(0xffffffffu, pr, off);
    }
    int node = n0 + sub;
    if (node < n) {
        g_f1[node * DOUT + j] = acc;
        if (j == 0) { g_el1[node] = pl; g_er1[node] = pr; }
    }
}

// -------- edge passes --------
template<int H>
__global__ void edge_max_k(const int* __restrict__ src, const int* __restrict__ dst,
                           const float* __restrict__ el, const float* __restrict__ er,
                           float* m, int E) {
    int idx = blockIdx.x * blockDim.x + threadIdx.x;
    if (idx >= E * H) return;
    int e = idx / H, h = idx - e * H;
    int s = src[e], d = dst[e];
    float v = lrelu02(el[s * H + h] + er[d * H + h]);
    atomicMaxF(&m[d * H + h], v);
}

template<int H>
__global__ void edge_sum_k(const int* __restrict__ src, const int* __restrict__ dst,
                           const float* __restrict__ el, const float* __restrict__ er,
                           const float* __restrict__ m, float* dden, int E) {
    int idx = blockIdx.x * blockDim.x + threadIdx.x;
    if (idx >= E * H) return;
    int e = idx / H, h = idx - e * H;
    int s = src[e], d = dst[e];
    float v = lrelu02(el[s * H + h] + er[d * H + h]);
    atomicAdd(&dden[d * H + h], __expf(v - m[d * H + h]));
}

template<int H>
__global__ void edge_scatter_k(const int* __restrict__ src, const int* __restrict__ dst,
                               const float* __restrict__ el, const float* __restrict__ er,
                               const float* __restrict__ m, const float* __restrict__ dden,
                               const float* __restrict__ f, float* out, int E) {
    constexpr int TPE = H * DOUT / 4;   // threads per edge (float4 each)
    int gt = blockIdx.x * blockDim.x + threadIdx.x;
    int e = gt / TPE;
    if (e >= E) return;
    int t = gt - e * TPE;
    int h = (t * 4) / DOUT;
    int s = src[e], d = dst[e];
    float v = lrelu02(el[s * H + h] + er[d * H + h]);
    float w = __expf(v - m[d * H + h]) / dden[d * H + h];
    const float4 fv = *(const float4*)&f[s * (H * DOUT) + t * 4];
    redAdd4(&out[d * (H * DOUT) + t * 4], w * fv.x, w * fv.y, w * fv.z, w * fv.w);
}

// -------- finalize --------
__global__ void finalize0_k(const float* __restrict__ b0, int n) {
    int i = blockIdx.x * blockDim.x + threadIdx.x;
    if (i >= n * F0DIM) return;
    float v = g_out0[i] + b0[i & 255];
    g_out0[i] = v > 0.f ? v : expm1f(v);   // ELU
}
__global__ void finalize1_k(const float* __restrict__ b1, int n) {
    int i = blockIdx.x * blockDim.x + threadIdx.x;
    if (i >= n * DOUT) return;
    g_h1[i] = g_out1[i] + b1[i & 31];      // H1 = 1 -> mean is identity
}

// -------- link predictor: one warp per (row, branch) --------
__global__ void predictor_k(const float* __restrict__ P1, const float* __restrict__ pb1,
                            const float* __restrict__ P2, const float* __restrict__ pb2,
                            const float* __restrict__ P3, const float* __restrict__ pb3,
                            float* __restrict__ out, int num_edge) {
    int w = (blockIdx.x * blockDim.x + threadIdx.x) >> 5;
    int lane = threadIdx.x & 31;
    if (w >= 2 * num_edge) return;
    int branch = w / num_edge;
    int i = w - branch * num_edge;
    const float* a = g_h1 + (size_t)i * DOUT;
    const float* b = g_h1 + (size_t)(num_edge * (1 + branch) + i) * DOUT;
    float z = a[lane] * b[lane];

    float acc = pb1[lane];
    #pragma unroll
    for (int k = 0; k < 32; k++)
        acc = fmaf(__shfl_sync(0xffffffffu, z, k), P1[k * 32 + lane], acc);
    z = fmaxf(acc, 0.f);

    acc = pb2[lane];
    #pragma unroll
    for (int k = 0; k < 32; k++)
        acc = fmaf(__shfl_sync(0xffffffffu, z, k), P2[k * 32 + lane], acc);
    z = fmaxf(acc, 0.f);

    float p = z * P3[lane];
    #pragma unroll
    for (int off = 16; off; off >>= 1) p += __shfl_xor_sync(0xffffffffu, p, off);
    if (lane == 0) out[branch * num_edge + i] = p + pb3[0];
}

// -------- launch --------
extern "C" void kernel_launch(void* const* d_in, const int* in_sizes, int n_in,
                              void* d_out, int out_size) {
    const float* x   = (const float*)d_in[0];
    const int*   src = (const int*)  d_in[1];
    const int*   dst = (const int*)  d_in[2];
    const float* W0  = (const float*)d_in[4];
    const float* al0 = (const float*)d_in[5];
    const float* ar0 = (const float*)d_in[6];
    const float* b0  = (const float*)d_in[7];
    const float* W1  = (const float*)d_in[8];
    const float* al1 = (const float*)d_in[9];
    const float* ar1 = (const float*)d_in[10];
    const float* b1  = (const float*)d_in[11];
    const float* P1  = (const float*)d_in[12];
    const float* pb1 = (const float*)d_in[13];
    const float* P2  = (const float*)d_in[14];
    const float* pb2 = (const float*)d_in[15];
    const float* P3  = (const float*)d_in[16];
    const float* pb3 = (const float*)d_in[17];
    float* out = (float*)d_out;

    int n = in_sizes[0] / DIN;   // 49998
    int E = in_sizes[1];         // 800000
    int num_edge = n / 3;        // neg_sample_ratio = 1

    float *p_el0, *p_er0, *p_m0, *p_d0, *p_f0, *p_out0;
    float *p_el1, *p_er1, *p_m1, *p_d1, *p_f1, *p_out1;
    cudaGetSymbolAddress((void**)&p_el0,  g_el0);
    cudaGetSymbolAddress((void**)&p_er0,  g_er0);
    cudaGetSymbolAddress((void**)&p_m0,   g_m0);
    cudaGetSymbolAddress((void**)&p_d0,   g_d0);
    cudaGetSymbolAddress((void**)&p_f0,   g_f0);
    cudaGetSymbolAddress((void**)&p_out0, g_out0);
    cudaGetSymbolAddress((void**)&p_el1,  g_el1);
    cudaGetSymbolAddress((void**)&p_er1,  g_er1);
    cudaGetSymbolAddress((void**)&p_m1,   g_m1);
    cudaGetSymbolAddress((void**)&p_d1,   g_d1);
    cudaGetSymbolAddress((void**)&p_f1,   g_f1);
    cudaGetSymbolAddress((void**)&p_out1, g_out1);

    const int T = 256;
    // ---- layer 0 ----
    init0_k<<<(n * F0DIM + T - 1) / T, T>>>(n);
    gemm0_k<<<(n + 31) / 32, T>>>(x, W0, al0, ar0, n);
    edge_max_k<HH0><<<(E * HH0 + T - 1) / T, T>>>(src, dst, p_el0, p_er0, p_m0, E);
    edge_sum_k<HH0><<<(E * HH0 + T - 1) / T, T>>>(src, dst, p_el0, p_er0, p_m0, p_d0, E);
    edge_scatter_k<HH0><<<(E * (HH0 * DOUT / 4) + T - 1) / T, T>>>(
        src, dst, p_el0, p_er0, p_m0, p_d0, p_f0, p_out0, E);
    finalize0_k<<<(n * F0DIM + T - 1) / T, T>>>(b0, n);
    // ---- layer 1 ----
    init1_k<<<(n * DOUT + T - 1) / T, T>>>(n);
    gemm1_k<<<(n + 7) / 8, T>>>(W1, al1, ar1, n);
    edge_max_k<1><<<(E + T - 1) / T, T>>>(src, dst, p_el1, p_er1, p_m1, E);
    edge_sum_k<1><<<(E + T - 1) / T, T>>>(src, dst, p_el1, p_er1, p_m1, p_d1, E);
    edge_scatter_k<1><<<(E * (DOUT / 4) + T - 1) / T, T>>>(
        src, dst, p_el1, p_er1, p_m1, p_d1, p_f1, p_out1, E);
    finalize1_k<<<(n * DOUT + T - 1) / T, T>>>(b1, n);
    // ---- predictor ----
    predictor_k<<<(2 * num_edge * 32 + T - 1) / T, T>>>(P1, pb1, P2, pb2, P3, pb3, out, num_edge);
}

// round 3
// speedup vs baseline: 1.3596x; 1.3596x over previous
#include <cuda_runtime.h>
#include <cuda_bf16.h>

#define N_NODES 49998
#define E_EDGES 800000
#define HH0 8
#define DIN 128
#define DOUT 32
#define F0DIM (HH0*DOUT)   /* 256 */
#define SCAN_B 1024
#define NBLK ((N_NODES + SCAN_B - 1) / SCAN_B)   /* 49 */

// -------- scratch (device globals; no allocation allowed) --------
__device__ float g_f0 [N_NODES*F0DIM];
__device__ float g_h0 [N_NODES*F0DIM];
__device__ float g_el0[N_NODES*HH0];
__device__ float g_er0[N_NODES*HH0];
__device__ float g_f1 [N_NODES*DOUT];
__device__ float g_h1 [N_NODES*DOUT];
__device__ float g_el1[N_NODES];
__device__ float g_er1[N_NODES];
__device__ int   g_deg[N_NODES];
__device__ int   g_cursor[N_NODES];
__device__ int   g_tmp[N_NODES];
__device__ int   g_rowptr[N_NODES+1];
__device__ int   g_part[64];
__device__ int   g_partoff[64];
__device__ int   g_csr_src[E_EDGES];

__device__ __forceinline__ float lrelu02(float v) { return v > 0.f ? v : 0.2f * v; }

// ================= CSR build =================
__global__ void zero_deg_k(int n) {
    int i = blockIdx.x * blockDim.x + threadIdx.x;
    if (i < n) g_deg[i] = 0;
}
__global__ void hist_k(const int* __restrict__ dst, int E) {
    int e = blockIdx.x * blockDim.x + threadIdx.x;
    if (e < E) atomicAdd(&g_deg[dst[e]], 1);
}
// per-block inclusive scan (Hillis-Steele over 1024)
__global__ void scan_block_k(int n) {
    __shared__ int sm[SCAN_B];
    int lt = threadIdx.x;
    int i  = blockIdx.x * SCAN_B + lt;
    sm[lt] = (i < n) ? g_deg[i] : 0;
    __syncthreads();
    #pragma unroll
    for (int off = 1; off < SCAN_B; off <<= 1) {
        int v = (lt >= off) ? sm[lt - off] : 0;
        __syncthreads();
        sm[lt] += v;
        __syncthreads();
    }
    if (i < n) g_tmp[i] = sm[lt];
    if (lt == SCAN_B - 1) g_part[blockIdx.x] = sm[lt];
}
__global__ void scan_top_k(int nblk) {
    __shared__ int sm[64];
    int lt = threadIdx.x;
    int v0 = (lt < nblk) ? g_part[lt] : 0;
    sm[lt] = v0;
    __syncthreads();
    #pragma unroll
    for (int off = 1; off < 64; off <<= 1) {
        int v = (lt >= off) ? sm[lt - off] : 0;
        __syncthreads();
        sm[lt] += v;
        __syncthreads();
    }
    g_partoff[lt] = sm[lt] - v0;   // exclusive block offset
}
__global__ void scan_add_k(int n, int E) {
    int i = blockIdx.x * blockDim.x + threadIdx.x;
    if (i < n) {
        int rp = g_tmp[i] - g_deg[i] + g_partoff[i >> 10];  // exclusive
        g_rowptr[i] = rp;
        g_cursor[i] = rp;    // cursor starts at row base
    }
    if (i == 0) g_rowptr[n] = E;
}
__global__ void fill_k(const int* __restrict__ src, const int* __restrict__ dst, int E) {
    int e = blockIdx.x * blockDim.x + threadIdx.x;
    if (e >= E) return;
    int d = dst[e];
    int pos = atomicAdd(&g_cursor[d], 1);
    g_csr_src[pos] = src[e];
}

// ================= layer-0 GEMM: f0 = x @ W0, el0/er0 =================
__global__ void gemm0_k(const float* __restrict__ x, const float* __restrict__ W0,
                        const float* __restrict__ al0, const float* __restrict__ ar0, int n) {
    __shared__ float xs[DIN][36];
    int n0 = blockIdx.x * 32;
    int t  = threadIdx.x;
    for (int i = t; i < 32 * DIN; i += 256) {
        int r = i >> 7, c = i & 127;
        int node = n0 + r;
        xs[c][r] = (node < n) ? x[node * DIN + c] : 0.f;
    }
    __syncthreads();

    float acc[32];
    #pragma unroll
    for (int i = 0; i < 32; i++) acc[i] = 0.f;

    for (int k = 0; k < DIN; k++) {
        float w = W0[k * F0DIM + t];
        const float4* xp = (const float4*)&xs[k][0];
        #pragma unroll
        for (int ii = 0; ii < 8; ii++) {
            float4 xv = xp[ii];
            acc[4*ii+0] = fmaf(xv.x, w, acc[4*ii+0]);
            acc[4*ii+1] = fmaf(xv.y, w, acc[4*ii+1]);
            acc[4*ii+2] = fmaf(xv.z, w, acc[4*ii+2]);
            acc[4*ii+3] = fmaf(xv.w, w, acc[4*ii+3]);
        }
    }

    int h = t >> 5, lane = t & 31;
    float alv = al0[t], arv = ar0[t];
    #pragma unroll
    for (int i = 0; i < 32; i++) {
        int node = n0 + i;
        float fv = acc[i];
        float pl = fv * alv, pr = fv * arv;
        #pragma unroll
        for (int off = 16; off; off >>= 1) {
            pl += __shfl_xor_sync(0xffffffffu, pl, off);
            pr += __shfl_xor_sync(0xffffffffu, pr, off);
        }
        if (node < n) {
            g_f0[(size_t)node * F0DIM + t] = fv;
            if (lane == 0) { g_el0[node * HH0 + h] = pl; g_er0[node * HH0 + h] = pr; }
        }
    }
}

// ================= layer-0 fused softmax + gather + bias + ELU =================
// one block (256 thr) per dst node; thread t owns column t (head h = t>>5)
__global__ void agg0_k(const float* __restrict__ b0, int n) {
    int d = blockIdx.x;
    int t = threadIdx.x;
    int row0 = g_rowptr[d], row1 = g_rowptr[d + 1];
    int h8 = t & 7, e8 = t >> 3, h32 = t >> 5;
    __shared__ int   s_src[32];
    __shared__ float s_w[32 * 8];    // [edge][head]
    __shared__ float sden[256];

    float acc = 0.f, denp = 0.f;
    float er = g_er0[d * HH0 + h8];

    for (int base = row0; base < row1; base += 32) {
        int cnt = min(32, row1 - base);
        __syncthreads();
        if (t < cnt) s_src[t] = g_csr_src[base + t];
        __syncthreads();
        if (e8 < cnt) {
            int s = s_src[e8];
            float v = lrelu02(__ldg(&g_el0[s * HH0 + h8]) + er);
            float w = __expf(v);      // no max-shift: scores tiny, ratio identical
            s_w[t] = w;               // t == e8*8 + h8
            denp += w;
        }
        __syncthreads();
        int i = 0;
        for (; i + 4 <= cnt; i += 4) {
            float w0 = s_w[(i+0)*8 + h32], w1 = s_w[(i+1)*8 + h32];
            float w2 = s_w[(i+2)*8 + h32], w3 = s_w[(i+3)*8 + h32];
            float a0 = __ldg(&g_f0[(size_t)s_src[i+0] * F0DIM + t]);
            float a1 = __ldg(&g_f0[(size_t)s_src[i+1] * F0DIM + t]);
            float a2 = __ldg(&g_f0[(size_t)s_src[i+2] * F0DIM + t]);
            float a3 = __ldg(&g_f0[(size_t)s_src[i+3] * F0DIM + t]);
            acc = fmaf(w0, a0, acc);
            acc = fmaf(w1, a1, acc);
            acc = fmaf(w2, a2, acc);
            acc = fmaf(w3, a3, acc);
        }
        for (; i < cnt; i++)
            acc = fmaf(s_w[i*8 + h32], __ldg(&g_f0[(size_t)s_src[i] * F0DIM + t]), acc);
    }

    sden[t] = denp;
    __syncthreads();
    #pragma unroll
    for (int strd = 128; strd >= 8; strd >>= 1) {
        if (t < strd) sden[t] += sden[t + strd];
        __syncthreads();
    }
    float den = sden[h32];
    float o = (row1 > row0) ? acc / den : 0.f;
    o += b0[t];
    g_h0[(size_t)d * F0DIM + t] = o > 0.f ? o : expm1f(o);   // ELU
}

// ================= layer-1 GEMM: f1 = h0 @ W1, el1/er1 =================
__global__ void gemm1_k(const float* __restrict__ W1,
                        const float* __restrict__ al1, const float* __restrict__ ar1, int n) {
    __shared__ float hs[8][F0DIM];
    int n0 = blockIdx.x * 8;
    int t  = threadIdx.x;
    for (int i = t; i < 8 * F0DIM; i += 256) {
        int r = i >> 8, c = i & 255;
        int node = n0 + r;
        hs[r][c] = (node < n) ? g_h0[(size_t)node * F0DIM + c] : 0.f;
    }
    __syncthreads();

    int j = t & 31, sub = t >> 5;
    float acc = 0.f;
    #pragma unroll 8
    for (int k = 0; k < F0DIM; k++) acc = fmaf(hs[sub][k], W1[k * DOUT + j], acc);

    float pl = acc * al1[j], pr = acc * ar1[j];
    #pragma unroll
    for (int off = 16; off; off >>= 1) {
        pl += __shfl_xor_sync(0xffffffffu, pl, off);
        pr += __shfl_xor_sync(0xffffffffu, pr, off);
    }
    int node = n0 + sub;
    if (node < n) {
        g_f1[(size_t)node * DOUT + j] = acc;
        if (j == 0) { g_el1[node] = pl; g_er1[node] = pr; }
    }
}

// ================= layer-1 fused softmax + gather + bias =================
// one warp per node
__global__ void agg1_k(const float* __restrict__ b1, int n) {
    int t = threadIdx.x, lane = t & 31;
    int node = blockIdx.x * 8 + (t >> 5);
    if (node >= n) return;
    int row0 = g_rowptr[node], row1 = g_rowptr[node + 1];
    float er = g_er1[node];
    float acc = 0.f, den = 0.f;
    for (int base = row0; base < row1; base += 32) {
        int cnt = min(32, row1 - base);
        int s = 0; float w = 0.f;
        if (lane < cnt) {
            s = g_csr_src[base + lane];
            float v = lrelu02(__ldg(&g_el1[s]) + er);
            w = __expf(v);
            den += w;
        }
        for (int i = 0; i < cnt; i++) {
            int   si = __shfl_sync(0xffffffffu, s, i);
            float wi = __shfl_sync(0xffffffffu, w, i);
            acc = fmaf(wi, __ldg(&g_f1[(size_t)si * DOUT + lane]), acc);
        }
    }
    #pragma unroll
    for (int off = 16; off; off >>= 1) den += __shfl_xor_sync(0xffffffffu, den, off);
    float o = (row1 > row0) ? acc / den : 0.f;
    g_h1[(size_t)node * DOUT + lane] = o + b1[lane];   // H1=1 -> mean is identity
}

// ================= link predictor =================
__global__ void predictor_k(const float* __restrict__ P1, const float* __restrict__ pb1,
                            const float* __restrict__ P2, const float* __restrict__ pb2,
                            const float* __restrict__ P3, const float* __restrict__ pb3,
                            float* __restrict__ out, int num_edge) {
    int w = (blockIdx.x * blockDim.x + threadIdx.x) >> 5;
    int lane = threadIdx.x & 31;
    if (w >= 2 * num_edge) return;
    int branch = w / num_edge;
    int i = w - branch * num_edge;
    const float* a = g_h1 + (size_t)i * DOUT;
    const float* b = g_h1 + (size_t)(num_edge * (1 + branch) + i) * DOUT;
    float z = a[lane] * b[lane];

    float acc = pb1[lane];
    #pragma unroll
    for (int k = 0; k < 32; k++)
        acc = fmaf(__shfl_sync(0xffffffffu, z, k), P1[k * 32 + lane], acc);
    z = fmaxf(acc, 0.f);

    acc = pb2[lane];
    #pragma unroll
    for (int k = 0; k < 32; k++)
        acc = fmaf(__shfl_sync(0xffffffffu, z, k), P2[k * 32 + lane], acc);
    z = fmaxf(acc, 0.f);

    float p = z * P3[lane];
    #pragma unroll
    for (int off = 16; off; off >>= 1) p += __shfl_xor_sync(0xffffffffu, p, off);
    if (lane == 0) out[branch * num_edge + i] = p + pb3[0];
}

// ================= launch =================
extern "C" void kernel_launch(void* const* d_in, const int* in_sizes, int n_in,
                              void* d_out, int out_size) {
    const float* x   = (const float*)d_in[0];
    const int*   src = (const int*)  d_in[1];
    const int*   dst = (const int*)  d_in[2];
    const float* W0  = (const float*)d_in[4];
    const float* al0 = (const float*)d_in[5];
    const float* ar0 = (const float*)d_in[6];
    const float* b0  = (const float*)d_in[7];
    const float* W1  = (const float*)d_in[8];
    const float* al1 = (const float*)d_in[9];
    const float* ar1 = (const float*)d_in[10];
    const float* b1  = (const float*)d_in[11];
    const float* P1  = (const float*)d_in[12];
    const float* pb1 = (const float*)d_in[13];
    const float* P2  = (const float*)d_in[14];
    const float* pb2 = (const float*)d_in[15];
    const float* P3  = (const float*)d_in[16];
    const float* pb3 = (const float*)d_in[17];
    float* out = (float*)d_out;

    int n = in_sizes[0] / DIN;   // 49998
    int E = in_sizes[1];         // 800000
    int num_edge = n / 3;        // neg_sample_ratio = 1

    const int T = 256;
    // ---- CSR build (by dst) ----
    zero_deg_k<<<(n + T - 1) / T, T>>>(n);
    hist_k<<<(E + T - 1) / T, T>>>(dst, E);
    scan_block_k<<<NBLK, SCAN_B>>>(n);
    scan_top_k<<<1, 64>>>(NBLK);
    scan_add_k<<<(n + T - 1) / T, T>>>(n, E);
    fill_k<<<(E + T - 1) / T, T>>>(src, dst, E);
    // ---- layer 0 ----
    gemm0_k<<<(n + 31) / 32, T>>>(x, W0, al0, ar0, n);
    agg0_k<<<n, T>>>(b0, n);
    // ---- layer 1 ----
    gemm1_k<<<(n + 7) / 8, T>>>(W1, al1, ar1, n);
    agg1_k<<<(n + 7) / 8, T>>>(b1, n);
    // ---- predictor ----
    predictor_k<<<(2 * num_edge * 32 + T - 1) / T, T>>>(P1, pb1, P2, pb2, P3, pb3, out, num_edge);
}

// round 4
// speedup vs baseline: 2.1106x; 1.5524x over previous
#include <cuda_runtime.h>
#include <cuda_bf16.h>

#define N_NODES 49998
#define E_EDGES 800000
#define HH0 8
#define DIN 128
#define DOUT 32
#define F0DIM (HH0*DOUT)   /* 256 */
#define SCAN_B 1024
#define NBLK ((N_NODES + SCAN_B - 1) / SCAN_B)   /* 49 */

typedef unsigned long long ull;

// -------- scratch (device globals; no allocation allowed) --------
__device__ float g_f0 [N_NODES*F0DIM];
__device__ float g_h0 [N_NODES*F0DIM];
__device__ float g_el0[N_NODES*HH0];
__device__ float g_er0[N_NODES*HH0];
__device__ float g_f1 [N_NODES*DOUT];
__device__ float g_h1 [N_NODES*DOUT];
__device__ float g_el1[N_NODES];
__device__ float g_er1[N_NODES];
__device__ int   g_deg[N_NODES];
__device__ int   g_cursor[N_NODES];
__device__ int   g_tmp[N_NODES];
__device__ int   g_rowptr[N_NODES+1];
__device__ int   g_part[64];
__device__ int   g_partoff[64];
__device__ int   g_csr_src[E_EDGES];

__device__ __forceinline__ float lrelu02(float v) { return v > 0.f ? v : 0.2f * v; }

// ---- packed fp32x2 helpers (exact fp32 semantics, 2x FFMA issue density) ----
__device__ __forceinline__ ull fma2(ull a, ull b, ull c) {
    ull d;
    asm("fma.rn.f32x2 %0, %1, %2, %3;" : "=l"(d) : "l"(a), "l"(b), "l"(c));
    return d;
}
__device__ __forceinline__ ull pack2(float a, float b) {
    ull r;
    asm("mov.b64 %0, {%1, %2};" : "=l"(r) : "r"(__float_as_uint(a)), "r"(__float_as_uint(b)));
    return r;
}
__device__ __forceinline__ ull dup2(float a) {
    ull r;
    asm("mov.b64 %0, {%1, %1};" : "=l"(r) : "r"(__float_as_uint(a)));
    return r;
}
__device__ __forceinline__ float2 unpack2(ull v) {
    unsigned lo, hi;
    asm("mov.b64 {%0, %1}, %2;" : "=r"(lo), "=r"(hi) : "l"(v));
    return make_float2(__uint_as_float(lo), __uint_as_float(hi));
}

// ================= CSR build =================
__global__ void zero_deg_k(int n) {
    int i = blockIdx.x * blockDim.x + threadIdx.x;
    if (i < n) g_deg[i] = 0;
}
__global__ void hist_k(const int* __restrict__ dst, int E) {
    int e = blockIdx.x * blockDim.x + threadIdx.x;
    if (e < E) atomicAdd(&g_deg[dst[e]], 1);
}
__global__ void scan_block_k(int n) {
    __shared__ int sm[SCAN_B];
    int lt = threadIdx.x;
    int i  = blockIdx.x * SCAN_B + lt;
    sm[lt] = (i < n) ? g_deg[i] : 0;
    __syncthreads();
    #pragma unroll
    for (int off = 1; off < SCAN_B; off <<= 1) {
        int v = (lt >= off) ? sm[lt - off] : 0;
        __syncthreads();
        sm[lt] += v;
        __syncthreads();
    }
    if (i < n) g_tmp[i] = sm[lt];
    if (lt == SCAN_B - 1) g_part[blockIdx.x] = sm[lt];
}
__global__ void scan_top_k(int nblk) {
    __shared__ int sm[64];
    int lt = threadIdx.x;
    int v0 = (lt < nblk) ? g_part[lt] : 0;
    sm[lt] = v0;
    __syncthreads();
    #pragma unroll
    for (int off = 1; off < 64; off <<= 1) {
        int v = (lt >= off) ? sm[lt - off] : 0;
        __syncthreads();
        sm[lt] += v;
        __syncthreads();
    }
    g_partoff[lt] = sm[lt] - v0;
}
__global__ void scan_add_k(int n, int E) {
    int i = blockIdx.x * blockDim.x + threadIdx.x;
    if (i < n) {
        int rp = g_tmp[i] - g_deg[i] + g_partoff[i >> 10];
        g_rowptr[i] = rp;
        g_cursor[i] = rp;
    }
    if (i == 0) g_rowptr[n] = E;
}
__global__ void fill_k(const int* __restrict__ src, const int* __restrict__ dst, int E) {
    int e = blockIdx.x * blockDim.x + threadIdx.x;
    if (e >= E) return;
    int d = dst[e];
    int pos = atomicAdd(&g_cursor[d], 1);
    g_csr_src[pos] = src[e];
}

// ================= layer-0 GEMM: f0 = x @ W0, el0/er0 =================
// grid (ceil(n/64), 4). block 128. thread tile: 4 nodes (tn, tn+16, tn+32, tn+48) x 8 cols.
#define XS_STRIDE 129
__global__ void __launch_bounds__(128) gemm0_k(
        const float* __restrict__ x, const float* __restrict__ W0,
        const float* __restrict__ al0, const float* __restrict__ ar0, int n) {
    __shared__ float xs[64 * XS_STRIDE];    // xs[node][k], stride 129 -> conflict-free reads
    __shared__ float s_el[64][2];
    __shared__ float s_er[64][2];
    int t  = threadIdx.x;
    int n0 = blockIdx.x * 64;
    int j0 = blockIdx.y * 64;

    // load x tile (coalesced reads, scalar smem writes)
    for (int i = t; i < 64 * 32; i += 128) {
        int r = i >> 5, c4 = i & 31;
        int node = n0 + r;
        float4 v = make_float4(0.f, 0.f, 0.f, 0.f);
        if (node < n) v = *(const float4*)&x[node * DIN + c4 * 4];
        float* xp = &xs[r * XS_STRIDE + c4 * 4];
        xp[0] = v.x; xp[1] = v.y; xp[2] = v.z; xp[3] = v.w;
    }
    if (t < 64) { s_el[t][0] = 0.f; s_el[t][1] = 0.f; s_er[t][0] = 0.f; s_er[t][1] = 0.f; }
    __syncthreads();

    int tn = t & 15, tc = t >> 4;       // tc 0..7
    int jb = j0 + tc * 8;

    ull acc[8][2];
    #pragma unroll
    for (int j = 0; j < 8; j++) { acc[j][0] = 0ull; acc[j][1] = 0ull; }

    const float* xr0 = &xs[(tn     ) * XS_STRIDE];
    const float* xr1 = &xs[(tn + 16) * XS_STRIDE];
    const float* xr2 = &xs[(tn + 32) * XS_STRIDE];
    const float* xr3 = &xs[(tn + 48) * XS_STRIDE];

    #pragma unroll 4
    for (int k = 0; k < DIN; k++) {
        ull xa = pack2(xr0[k], xr1[k]);
        ull xb = pack2(xr2[k], xr3[k]);
        const float4* wp = (const float4*)&W0[k * F0DIM + jb];
        float4 w0 = wp[0], w1 = wp[1];
        float wv[8] = {w0.x, w0.y, w0.z, w0.w, w1.x, w1.y, w1.z, w1.w};
        #pragma unroll
        for (int j = 0; j < 8; j++) {
            ull w2 = dup2(wv[j]);
            acc[j][0] = fma2(xa, w2, acc[j][0]);
            acc[j][1] = fma2(xb, w2, acc[j][1]);
        }
    }

    // epilogue: unpack, el/er partials, store f0
    float f[4][8];
    #pragma unroll
    for (int j = 0; j < 8; j++) {
        float2 a = unpack2(acc[j][0]);
        float2 b = unpack2(acc[j][1]);
        f[0][j] = a.x; f[1][j] = a.y; f[2][j] = b.x; f[3][j] = b.y;
    }
    float pl[4] = {0.f,0.f,0.f,0.f}, pr[4] = {0.f,0.f,0.f,0.f};
    #pragma unroll
    for (int j = 0; j < 8; j++) {
        float alv = al0[jb + j], arv = ar0[jb + j];
        #pragma unroll
        for (int i = 0; i < 4; i++) {
            pl[i] = fmaf(f[i][j], alv, pl[i]);
            pr[i] = fmaf(f[i][j], arv, pr[i]);
        }
    }
    int hl = tc >> 2;   // local head (2 heads per 64-col block)
    #pragma unroll
    for (int i = 0; i < 4; i++) {
        int rloc = tn + 16 * i;
        int node = n0 + rloc;
        if (node < n) {
            float* dst = &g_f0[(size_t)node * F0DIM + jb];
            *(float4*)dst       = make_float4(f[i][0], f[i][1], f[i][2], f[i][3]);
            *(float4*)(dst + 4) = make_float4(f[i][4], f[i][5], f[i][6], f[i][7]);
            atomicAdd(&s_el[rloc][hl], pl[i]);
            atomicAdd(&s_er[rloc][hl], pr[i]);
        }
    }
    __syncthreads();
    {
        int r = t >> 1, h2 = t & 1;
        int node = n0 + r;
        if (node < n) {
            g_el0[node * HH0 + blockIdx.y * 2 + h2] = s_el[r][h2];
            g_er0[node * HH0 + blockIdx.y * 2 + h2] = s_er[r][h2];
        }
    }
}

// ================= layer-0 fused softmax + gather + bias + ELU =================
// warp per dst node; lane l owns cols 8l..8l+7 (head h = l>>2). No block sync.
__global__ void __launch_bounds__(256) agg0_k(const float* __restrict__ b0, int n) {
    int t = threadIdx.x, l = t & 31;
    int d = blockIdx.x * 8 + (t >> 5);
    if (d >= n) return;
    int row0 = g_rowptr[d], row1 = g_rowptr[d + 1];
    int h = l >> 2;
    float er = g_er0[d * HH0 + h];

    ull acc[4] = {0ull, 0ull, 0ull, 0ull};
    float den = 0.f;

    #pragma unroll 2
    for (int e = row0; e < row1; e++) {
        int s = __ldg(&g_csr_src[e]);
        float w = __expf(lrelu02(__ldg(&g_el0[s * HH0 + h]) + er));
        den += w;
        ull w2 = dup2(w);
        const ulonglong2* p = (const ulonglong2*)&g_f0[(size_t)s * F0DIM + 8 * l];
        ulonglong2 va = __ldg(&p[0]);
        ulonglong2 vb = __ldg(&p[1]);
        acc[0] = fma2(va.x, w2, acc[0]);
        acc[1] = fma2(va.y, w2, acc[1]);
        acc[2] = fma2(vb.x, w2, acc[2]);
        acc[3] = fma2(vb.y, w2, acc[3]);
    }

    float inv = (row1 > row0) ? 1.f / den : 0.f;
    const float4* bp = (const float4*)&b0[8 * l];
    float4 ba = bp[0], bb = bp[1];
    float o[8];
    float2 u0 = unpack2(acc[0]), u1 = unpack2(acc[1]);
    float2 u2 = unpack2(acc[2]), u3 = unpack2(acc[3]);
    o[0] = u0.x * inv + ba.x; o[1] = u0.y * inv + ba.y;
    o[2] = u1.x * inv + ba.z; o[3] = u1.y * inv + ba.w;
    o[4] = u2.x * inv + bb.x; o[5] = u2.y * inv + bb.y;
    o[6] = u3.x * inv + bb.z; o[7] = u3.y * inv + bb.w;
    #pragma unroll
    for (int i = 0; i < 8; i++) o[i] = o[i] > 0.f ? o[i] : expm1f(o[i]);   // ELU
    float* dst = &g_h0[(size_t)d * F0DIM + 8 * l];
    *(float4*)dst       = make_float4(o[0], o[1], o[2], o[3]);
    *(float4*)(dst + 4) = make_float4(o[4], o[5], o[6], o[7]);
}

// ================= layer-1 GEMM: f1 = h0 @ W1, el1/er1 =================
// grid ceil(n/64). block 128. thread tile: 4 nodes x 4 cols. K=256 in 2 chunks of 128.
__global__ void __launch_bounds__(128) gemm1_k(
        const float* __restrict__ W1,
        const float* __restrict__ al1, const float* __restrict__ ar1, int n) {
    __shared__ float hs[64 * XS_STRIDE];
    __shared__ float s_el[64];
    __shared__ float s_er[64];
    int t  = threadIdx.x;
    int n0 = blockIdx.x * 64;
    int tn = t & 15, tc = t >> 4;       // tc 0..7, cols 4tc..4tc+3
    int jb = tc * 4;

    if (t < 64) { s_el[t] = 0.f; s_er[t] = 0.f; }

    ull acc[4][2];
    #pragma unroll
    for (int j = 0; j < 4; j++) { acc[j][0] = 0ull; acc[j][1] = 0ull; }

    const float* hr0 = &hs[(tn     ) * XS_STRIDE];
    const float* hr1 = &hs[(tn + 16) * XS_STRIDE];
    const float* hr2 = &hs[(tn + 32) * XS_STRIDE];
    const float* hr3 = &hs[(tn + 48) * XS_STRIDE];

    for (int c = 0; c < 2; c++) {
        __syncthreads();
        for (int i = t; i < 64 * 32; i += 128) {
            int r = i >> 5, c4 = i & 31;
            int node = n0 + r;
            float4 v = make_float4(0.f, 0.f, 0.f, 0.f);
            if (node < n) v = *(const float4*)&g_h0[(size_t)node * F0DIM + c * 128 + c4 * 4];
            float* hp = &hs[r * XS_STRIDE + c4 * 4];
            hp[0] = v.x; hp[1] = v.y; hp[2] = v.z; hp[3] = v.w;
        }
        __syncthreads();
        #pragma unroll 4
        for (int k = 0; k < 128; k++) {
            ull xa = pack2(hr0[k], hr1[k]);
            ull xb = pack2(hr2[k], hr3[k]);
            float4 w = *(const float4*)&W1[(c * 128 + k) * DOUT + jb];
            float wv[4] = {w.x, w.y, w.z, w.w};
            #pragma unroll
            for (int j = 0; j < 4; j++) {
                ull w2 = dup2(wv[j]);
                acc[j][0] = fma2(xa, w2, acc[j][0]);
                acc[j][1] = fma2(xb, w2, acc[j][1]);
            }
        }
    }

    float f[4][4];
    #pragma unroll
    for (int j = 0; j < 4; j++) {
        float2 a = unpack2(acc[j][0]);
        float2 b = unpack2(acc[j][1]);
        f[0][j] = a.x; f[1][j] = a.y; f[2][j] = b.x; f[3][j] = b.y;
    }
    float pl[4] = {0.f,0.f,0.f,0.f}, pr[4] = {0.f,0.f,0.f,0.f};
    #pragma unroll
    for (int j = 0; j < 4; j++) {
        float alv = al1[jb + j], arv = ar1[jb + j];
        #pragma unroll
        for (int i = 0; i < 4; i++) {
            pl[i] = fmaf(f[i][j], alv, pl[i]);
            pr[i] = fmaf(f[i][j], arv, pr[i]);
        }
    }
    #pragma unroll
    for (int i = 0; i < 4; i++) {
        int rloc = tn + 16 * i;
        int node = n0 + rloc;
        if (node < n) {
            *(float4*)&g_f1[(size_t)node * DOUT + jb] =
                make_float4(f[i][0], f[i][1], f[i][2], f[i][3]);
            atomicAdd(&s_el[rloc], pl[i]);
            atomicAdd(&s_er[rloc], pr[i]);
        }
    }
    __syncthreads();
    if (t < 64) {
        int node = n0 + t;
        if (node < n) { g_el1[node] = s_el[t]; g_er1[node] = s_er[t]; }
    }
}

// ================= layer-1 fused softmax + gather + bias =================
// warp per node; lane = col; redundant broadcast weight compute (free in SIMT).
__global__ void __launch_bounds__(256) agg1_k(const float* __restrict__ b1, int n) {
    int t = threadIdx.x, lane = t & 31;
    int node = blockIdx.x * 8 + (t >> 5);
    if (node >= n) return;
    int row0 = g_rowptr[node], row1 = g_rowptr[node + 1];
    float er = g_er1[node];
    float acc = 0.f, den = 0.f;
    #pragma unroll 2
    for (int e = row0; e < row1; e++) {
        int s = __ldg(&g_csr_src[e]);
        float w = __expf(lrelu02(__ldg(&g_el1[s]) + er));
        den += w;
        acc = fmaf(w, __ldg(&g_f1[(size_t)s * DOUT + lane]), acc);
    }
    float o = (row1 > row0) ? acc / den : 0.f;
    g_h1[(size_t)node * DOUT + lane] = o + b1[lane];
}

// ================= link predictor =================
__global__ void predictor_k(const float* __restrict__ P1, const float* __restrict__ pb1,
                            const float* __restrict__ P2, const float* __restrict__ pb2,
                            const float* __restrict__ P3, const float* __restrict__ pb3,
                            float* __restrict__ out, int num_edge) {
    int w = (blockIdx.x * blockDim.x + threadIdx.x) >> 5;
    int lane = threadIdx.x & 31;
    if (w >= 2 * num_edge) return;
    int branch = w / num_edge;
    int i = w - branch * num_edge;
    const float* a = g_h1 + (size_t)i * DOUT;
    const float* b = g_h1 + (size_t)(num_edge * (1 + branch) + i) * DOUT;
    float z = a[lane] * b[lane];

    float acc = pb1[lane];
    #pragma unroll
    for (int k = 0; k < 32; k++)
        acc = fmaf(__shfl_sync(0xffffffffu, z, k), P1[k * 32 + lane], acc);
    z = fmaxf(acc, 0.f);

    acc = pb2[lane];
    #pragma unroll
    for (int k = 0; k < 32; k++)
        acc = fmaf(__shfl_sync(0xffffffffu, z, k), P2[k * 32 + lane], acc);
    z = fmaxf(acc, 0.f);

    float p = z * P3[lane];
    #pragma unroll
    for (int off = 16; off; off >>= 1) p += __shfl_xor_sync(0xffffffffu, p, off);
    if (lane == 0) out[branch * num_edge + i] = p + pb3[0];
}

// ================= launch =================
extern "C" void kernel_launch(void* const* d_in, const int* in_sizes, int n_in,
                              void* d_out, int out_size) {
    const float* x   = (const float*)d_in[0];
    const int*   src = (const int*)  d_in[1];
    const int*   dst = (const int*)  d_in[2];
    const float* W0  = (const float*)d_in[4];
    const float* al0 = (const float*)d_in[5];
    const float* ar0 = (const float*)d_in[6];
    const float* b0  = (const float*)d_in[7];
    const float* W1  = (const float*)d_in[8];
    const float* al1 = (const float*)d_in[9];
    const float* ar1 = (const float*)d_in[10];
    const float* b1  = (const float*)d_in[11];
    const float* P1  = (const float*)d_in[12];
    const float* pb1 = (const float*)d_in[13];
    const float* P2  = (const float*)d_in[14];
    const float* pb2 = (const float*)d_in[15];
    const float* P3  = (const float*)d_in[16];
    const float* pb3 = (const float*)d_in[17];
    float* out = (float*)d_out;

    int n = in_sizes[0] / DIN;   // 49998
    int E = in_sizes[1];         // 800000
    int num_edge = n / 3;        // neg_sample_ratio = 1

    const int T = 256;
    // ---- CSR build (by dst) ----
    zero_deg_k<<<(n + T - 1) / T, T>>>(n);
    hist_k<<<(E + T - 1) / T, T>>>(dst, E);
    scan_block_k<<<NBLK, SCAN_B>>>(n);
    scan_top_k<<<1, 64>>>(NBLK);
    scan_add_k<<<(n + T - 1) / T, T>>>(n, E);
    fill_k<<<(E + T - 1) / T, T>>>(src, dst, E);
    // ---- layer 0 ----
    gemm0_k<<<dim3((n + 63) / 64, 4), 128>>>(x, W0, al0, ar0, n);
    agg0_k<<<(n + 7) / 8, T>>>(b0, n);
    // ---- layer 1 ----
    gemm1_k<<<(n + 63) / 64, 128>>>(W1, al1, ar1, n);
    agg1_k<<<(n + 7) / 8, T>>>(b1, n);
    // ---- predictor ----
    predictor_k<<<(2 * num_edge * 32 + T - 1) / T, T>>>(P1, pb1, P2, pb2, P3, pb3, out, num_edge);
}